// round 1
// baseline (speedup 1.0000x reference)
#include <cuda_runtime.h>
#include <math.h>

#define BB 512
#define TT 16
#define DD 256
#define LL 16
#define NTGT 32

// ---------------- scratch (device globals; no allocations allowed) ----------
__device__ float g_emb[BB * TT * DD];                 // [b][t][d]   8 MB
__device__ float g_f[(size_t)LL * BB * TT * DD];      // [l][b][t][d] 128 MB
__device__ float g_o[BB * DD];
__device__ float g_z[BB * DD];

// ---------------- 1) gather item embeddings --------------------------------
__global__ void gather_emb_kernel(const int* __restrict__ seq,
                                  const float* __restrict__ item_emb) {
    int row = blockIdx.x;                 // b*T + t
    int idx = seq[row];
    const float4* src = (const float4*)(item_emb + (size_t)idx * DD);
    float4* dst = (float4*)(g_emb + (size_t)row * DD);
    dst[threadIdx.x] = src[threadIdx.x];  // 64 threads * float4 = 256 floats
}

// ---------------- 2) conv einsum + relu+sigmoid gate ------------------------
// grid: (D/BN, B/BSUB, L). block 256 threads.
// block computes conv_out[l, b0..b0+7, t=0..15, c0..c0+127], i.e. a 128x128 tile
// of the GEMM  A[(b,t), (m,d)] * W[l][(m,d)][c],  A[(b,t),(m,d)] = emb[b, t-m, d].
#define BN   128
#define BSUB 8
#define KC   64
#define EPAD 257     // 16*257 row stride => bank-conflict-free t-indexed loads
#define WPAD 132     // 128 cols + pad, multiple of 4 for float4

__global__ void __launch_bounds__(256, 1)
conv_gate_kernel(const float* __restrict__ conv_w,
                 const float* __restrict__ conv_b) {
    extern __shared__ float sh[];
    float* emb_s = sh;                         // [BSUB][TT][EPAD]
    float* w_s   = sh + BSUB * TT * EPAD;      // [KC][WPAD] (d-major, transposed)

    const int l  = blockIdx.z;
    const int b0 = blockIdx.y * BSUB;
    const int c0 = blockIdx.x * BN;
    const int tid = threadIdx.x;
    const int tn = tid & 15;     // c-group: owns c = c0 + tn*8 + j, j=0..7
    const int tm = tid >> 4;     // t index: owns rows (bb, t=tm), bb=0..7

    // ---- stage emb for the 8 b's (whole A panel, kept resident) ----
    for (int it = tid; it < BSUB * TT * (DD / 4); it += 256) {
        int d4  = it & (DD / 4 - 1);
        int row = it >> 6;                         // bb*16 + t
        int bb = row >> 4, t = row & 15;
        float4 v = ((const float4*)g_emb)[(((size_t)(b0 + bb)) * TT + t) * (DD / 4) + d4];
        float* p = emb_s + (bb * TT + t) * EPAD + d4 * 4;
        p[0] = v.x; p[1] = v.y; p[2] = v.z; p[3] = v.w;
    }

    float acc[8][8];
#pragma unroll
    for (int i = 0; i < 8; i++)
#pragma unroll
        for (int j = 0; j < 8; j++) acc[i][j] = 0.f;

    for (int m = 0; m <= l; ++m) {
        const float* wbase = conv_w + (((size_t)l * LL + m) * DD + c0) * DD;  // [c][d]
        const bool active = (tm >= m);        // t-m < 0 taps are structurally zero
        const int trow = tm - m;

        for (int dc = 0; dc < DD; dc += KC) {
            __syncthreads();
            // stage W[l][m][c0..c0+127][dc..dc+63] transposed into w_s[d][c]
            for (int it = tid; it < BN * (KC / 4); it += 256) {
                int d4 = it & (KC / 4 - 1);   // 0..15
                int ci = it >> 4;             // 0..127
                float4 v = *(const float4*)(wbase + (size_t)ci * DD + dc + d4 * 4);
                w_s[(d4 * 4 + 0) * WPAD + ci] = v.x;
                w_s[(d4 * 4 + 1) * WPAD + ci] = v.y;
                w_s[(d4 * 4 + 2) * WPAD + ci] = v.z;
                w_s[(d4 * 4 + 3) * WPAD + ci] = v.w;
            }
            __syncthreads();

            if (active) {
                const float* arow = emb_s + trow * EPAD + dc;   // + i*TT*EPAD per bb
#pragma unroll 8
                for (int kk = 0; kk < KC; ++kk) {
                    float a[8];
#pragma unroll
                    for (int i = 0; i < 8; i++) a[i] = arow[i * TT * EPAD + kk];
                    const float4* wrow = (const float4*)(w_s + kk * WPAD);
                    float4 bv0 = wrow[tn * 2];
                    float4 bv1 = wrow[tn * 2 + 1];
                    float bvals[8] = {bv0.x, bv0.y, bv0.z, bv0.w,
                                      bv1.x, bv1.y, bv1.z, bv1.w};
#pragma unroll
                    for (int i = 0; i < 8; i++)
#pragma unroll
                        for (int j = 0; j < 8; j++)
                            acc[i][j] = fmaf(a[i], bvals[j], acc[i][j]);
                }
            }
        }
    }

    // ---- epilogue: + bias, relu, sigmoid; store gate f[l][b][t][d] ----
    float bias[8];
#pragma unroll
    for (int j = 0; j < 8; j++) bias[j] = conv_b[l * DD + c0 + tn * 8 + j];

    float* fb = g_f + (((size_t)l * BB + b0) * TT + tm) * DD + c0 + tn * 8;
#pragma unroll
    for (int i = 0; i < 8; i++) {
        float vals[8];
#pragma unroll
        for (int j = 0; j < 8; j++) {
            float x = acc[i][j] + bias[j];
            float xr = x > 0.f ? x : 0.f;
            vals[j] = 1.f / (1.f + expf(-xr));
        }
        float4* dst = (float4*)(fb + (size_t)i * TT * DD);
        dst[0] = make_float4(vals[0], vals[1], vals[2], vals[3]);
        dst[1] = make_float4(vals[4], vals[5], vals[6], vals[7]);
    }
}

// ---------------- 3) QRNN fo-pool chain (3 passes) + sum over l,t ----------
__global__ void qrnn_kernel() {
    int b = blockIdx.x;
    int d = threadIdx.x;
    float x[TT];
#pragma unroll
    for (int t = 0; t < TT; t++) x[t] = g_emb[((size_t)b * TT + t) * DD + d];

    float o = 0.f;
    for (int l = 0; l < LL; l++) {
        const float* fp = g_f + (((size_t)l * BB + b) * TT) * DD + d;
        float h1 = 0.f, h2 = 0.f, h3 = 0.f;
#pragma unroll
        for (int t = 0; t < TT; t++) {
            float f = fp[(size_t)t * DD];
            float g = 1.f - f;
            h1 = f * x[t] + g * h1;
            h2 = f * h1  + g * h2;
            h3 = f * h2  + g * h3;
            o += h3;
        }
    }
    g_o[(size_t)b * DD + d] = o;
}

// ---------------- 4) z = [o, user_emb] @ fc1_w^T + fc1_b -------------------
// grid (B/8, D/8), block 256 (8 warps); warp w computes output row i=i0+w for 8 b's.
__global__ void fc_kernel(const int* __restrict__ user_var,
                          const float* __restrict__ user_emb,
                          const float* __restrict__ fc1_w,
                          const float* __restrict__ fc1_b) {
    __shared__ float cat_s[8][2 * DD];
    int b0 = blockIdx.x * 8;
    int i0 = blockIdx.y * 8;
    int tid = threadIdx.x;

    for (int it = tid; it < 8 * (2 * DD / 4); it += 256) {   // 1024 float4
        int bb = it >> 7;
        int j4 = it & 127;
        float4 v;
        if (j4 < DD / 4)
            v = ((const float4*)(g_o + (size_t)(b0 + bb) * DD))[j4];
        else
            v = ((const float4*)(user_emb + (size_t)user_var[b0 + bb] * DD))[j4 - DD / 4];
        *(float4*)&cat_s[bb][j4 * 4] = v;
    }
    __syncthreads();

    int warp = tid >> 5, lane = tid & 31;
    int i = i0 + warp;
    float accv[8];
#pragma unroll
    for (int bb = 0; bb < 8; bb++) accv[bb] = 0.f;

    for (int j = lane; j < 2 * DD; j += 32) {
        float w = fc1_w[(size_t)i * (2 * DD) + j];
#pragma unroll
        for (int bb = 0; bb < 8; bb++) accv[bb] += w * cat_s[bb][j];
    }
#pragma unroll
    for (int bb = 0; bb < 8; bb++) {
        float v = accv[bb];
#pragma unroll
        for (int off = 16; off; off >>= 1) v += __shfl_down_sync(0xffffffffu, v, off);
        if (lane == 0) g_z[(size_t)(b0 + bb) * DD + i] = v + fc1_b[i];
    }
}

// ---------------- 5) res[b,n] = W2[item_var[b,n]] . z[b] + b2 ---------------
__global__ void out_kernel(const int* __restrict__ item_var,
                           const float* __restrict__ W2,
                           const float* __restrict__ b2,
                           float* __restrict__ out) {
    int gw = (blockIdx.x * blockDim.x + threadIdx.x) >> 5;
    int lane = threadIdx.x & 31;
    if (gw >= BB * NTGT) return;
    int b = gw >> 5;
    int iv = item_var[gw];
    const float* w = W2 + (size_t)iv * DD;
    const float* zz = g_z + (size_t)b * DD;
    float acc = 0.f;
    for (int d = lane; d < DD; d += 32) acc += w[d] * zz[d];
#pragma unroll
    for (int off = 16; off; off >>= 1) acc += __shfl_down_sync(0xffffffffu, acc, off);
    if (lane == 0) out[gw] = acc + b2[iv];
}

// ---------------- launch ----------------------------------------------------
extern "C" void kernel_launch(void* const* d_in, const int* in_sizes, int n_in,
                              void* d_out, int out_size) {
    const int*   seq_var  = (const int*)d_in[0];
    const int*   user_var = (const int*)d_in[1];
    const int*   item_var = (const int*)d_in[2];
    const float* item_emb = (const float*)d_in[3];
    const float* user_emb = (const float*)d_in[4];
    const float* conv_w   = (const float*)d_in[5];
    const float* conv_b   = (const float*)d_in[6];
    const float* fc1_w    = (const float*)d_in[7];
    const float* fc1_b    = (const float*)d_in[8];
    const float* W2       = (const float*)d_in[9];
    const float* b2       = (const float*)d_in[10];
    float* out = (float*)d_out;

    gather_emb_kernel<<<BB * TT, 64>>>(seq_var, item_emb);

    int smem = (BSUB * TT * EPAD + KC * WPAD) * (int)sizeof(float);
    cudaFuncSetAttribute(conv_gate_kernel,
                         cudaFuncAttributeMaxDynamicSharedMemorySize, smem);
    dim3 cgrid(DD / BN, BB / BSUB, LL);
    conv_gate_kernel<<<cgrid, 256, smem>>>(conv_w, conv_b);

    qrnn_kernel<<<BB, DD>>>();
    fc_kernel<<<dim3(BB / 8, DD / 8), 256>>>(user_var, user_emb, fc1_w, fc1_b);
    out_kernel<<<(BB * NTGT * 32) / 256, 256>>>(item_var, W2, b2, out);
}

// round 3
// speedup vs baseline: 7.5424x; 7.5424x over previous
#include <cuda_runtime.h>
#include <cuda_bf16.h>
#include <math.h>
#include <stdint.h>

#define BB 512
#define TT 16
#define DD 256
#define LL 16
#define NTGT 32
#define NROW (BB*TT)

// ---------------- scratch (device globals) ----------------------------------
__device__ float          g_emb  [NROW*DD];            // fp32 emb     8 MB
__device__ __nv_bfloat16  g_embh [NROW*DD];            // bf16 emb     4 MB
__device__ __nv_bfloat16  g_wh   [LL*LL*DD*DD];        // bf16 conv_w 33.5 MB
__device__ float          g_opart[LL*BB*DD];           // per-l o      8 MB
__device__ float          g_o    [BB*DD];
__device__ float          g_z    [BB*DD];

// ---------------- helpers ----------------------------------------------------
__device__ __forceinline__ uint32_t smem_u32(const void* p) {
    uint32_t a;
    asm("{ .reg .u64 t; cvta.to.shared.u64 t, %1; cvt.u32.u64 %0, t; }"
        : "=r"(a) : "l"(p));
    return a;
}
__device__ __forceinline__ void cpa16(uint32_t s, const void* g) {
    asm volatile("cp.async.cg.shared.global [%0], [%1], 16;"
                 :: "r"(s), "l"(g) : "memory");
}
#define CP_COMMIT() asm volatile("cp.async.commit_group;" ::: "memory")

__device__ __forceinline__ void ldsm4(uint32_t (&r)[4], uint32_t a) {
    asm volatile("ldmatrix.sync.aligned.m8n8.x4.shared.b16 {%0,%1,%2,%3}, [%4];"
                 : "=r"(r[0]), "=r"(r[1]), "=r"(r[2]), "=r"(r[3]) : "r"(a));
}
__device__ __forceinline__ void mma16816(float (&c)[4], const uint32_t (&a)[4],
                                         uint32_t b0, uint32_t b1) {
    asm volatile(
        "mma.sync.aligned.m16n8k16.row.col.f32.bf16.bf16.f32 "
        "{%0,%1,%2,%3}, {%4,%5,%6,%7}, {%8,%9}, {%0,%1,%2,%3};"
        : "+f"(c[0]), "+f"(c[1]), "+f"(c[2]), "+f"(c[3])
        : "r"(a[0]), "r"(a[1]), "r"(a[2]), "r"(a[3]), "r"(b0), "r"(b1));
}

// sigmoid for x>=0, tiny-|x| fast path (conv_out magnitudes are ~<0.1)
__device__ __forceinline__ float sigmoid_pos(float x) {
    if (x < 0.25f) {
        float x2 = x * x;
        // 0.5 + x/4 - x^3/48 + x^5/480  (err < 2e-9 on [0,0.25])
        float p = fmaf(x2, 1.0f / 480.0f, -1.0f / 48.0f);
        p = fmaf(x2, p, 0.25f);
        return fmaf(x, p, 0.5f);
    }
    return 1.0f / (1.0f + expf(-x));
}

// ---------------- 0a) gather item embeddings (fp32 + bf16) ------------------
__global__ void gather_emb_kernel(const int* __restrict__ seq,
                                  const float* __restrict__ item_emb) {
    int row = blockIdx.x;
    int idx = seq[row];
    float4 v = ((const float4*)(item_emb + (size_t)idx * DD))[threadIdx.x];
    ((float4*)(g_emb + (size_t)row * DD))[threadIdx.x] = v;
    __nv_bfloat162 p0 = __floats2bfloat162_rn(v.x, v.y);
    __nv_bfloat162 p1 = __floats2bfloat162_rn(v.z, v.w);
    __nv_bfloat162* dh = (__nv_bfloat162*)g_embh + (size_t)row * (DD / 2);
    dh[threadIdx.x * 2]     = p0;
    dh[threadIdx.x * 2 + 1] = p1;
}

// ---------------- 0b) conv_w fp32 -> bf16 ------------------------------------
__global__ void wconv_kernel(const float* __restrict__ conv_w) {
    size_t i = (size_t)blockIdx.x * blockDim.x + threadIdx.x;
    float4 v = ((const float4*)conv_w)[i];
    __nv_bfloat162* d = (__nv_bfloat162*)g_wh;
    d[2 * i]     = __floats2bfloat162_rn(v.x, v.y);
    d[2 * i + 1] = __floats2bfloat162_rn(v.z, v.w);
}

// ---------------- 1) fused windowed GEMM + gate + QRNN -----------------------
// CTA: l fixed, 8 b's x 16 t (128 M-rows) x 128 c's. K = (m<=l) x 256 d.
// smem: emb_s [128 rows][264 bf16]  (stride 528B, +4-bank skew)
//       zero row 528B
//       Bbuf[2] [128 c][72 bf16]    (stride 144B)
#define EST_B   528                   // emb_s row stride bytes
#define BST_B   144                   // B row stride bytes
#define EMB_SZ  (128*EST_B)           // 67584
#define ZOFF    EMB_SZ
#define B_OFF0  (EMB_SZ + 528)        // 68112 (16B aligned)
#define B_SZ    (128*BST_B)           // 18432
#define SMEM_REQ (B_OFF0 + 2*B_SZ)    // 104976

__global__ void __launch_bounds__(256, 2)
conv_fused_kernel(const float* __restrict__ conv_b) {
    extern __shared__ char smp[];
    const uint32_t sb = smem_u32(smp);
    const int tid = threadIdx.x, wid = tid >> 5, lane = tid & 31;
    const int warpM = wid >> 2, warpN = wid & 3;

    const int l  = 15 - blockIdx.z;
    const int b0 = blockIdx.y * 8;
    const int c0 = blockIdx.x * 128;

    // ---- stage A panel: 128 rows x 256 bf16 (512B payload, 528B stride) ----
    {
        const uint4* src = (const uint4*)g_embh + (size_t)b0 * TT * 32;
        for (int it = 0; it < 16; ++it) {
            int i = tid + it * 256;          // 4096 uint4
            int r = i >> 5, q = i & 31;
            uint4 v = src[r * 32 + q];
            *(uint4*)(smp + r * EST_B + q * 16) = v;
        }
        if (tid < 33) *(uint4*)(smp + ZOFF + tid * 16) = make_uint4(0, 0, 0, 0);
    }

    // ---- lane constants for ldmatrix address generation ----
    const int t_ln  = (lane & 7) + ((lane >> 3) & 1) * 8;  // A row-in-16
    const int kh_a  = lane >> 4;                            // A k-half
    const int n_ln  = ((lane >> 4) << 3) + (lane & 7);      // B row-in-16
    const int kh_b  = (lane >> 3) & 1;                      // B k-half

    const __nv_bfloat16* Wl = g_wh + (size_t)l * LL * DD * DD + (size_t)c0 * DD;

    float acc[4][4][4];
#pragma unroll
    for (int i = 0; i < 4; i++)
#pragma unroll
        for (int j = 0; j < 4; j++)
#pragma unroll
            for (int k = 0; k < 4; k++) acc[i][j][k] = 0.f;

    const int nch = (l + 1) * 4;   // chunks: (tap m) x (4 x 64-wide d)

    // B chunk loader: 128 c-rows x 64 bf16
    auto issueB = [&](int ch) {
        int m = ch >> 2, dk = ch & 3;
        const __nv_bfloat16* wb = Wl + (size_t)m * DD * DD + dk * 64;
        uint32_t sdst = sb + B_OFF0 + (ch & 1) * B_SZ;
#pragma unroll
        for (int it = 0; it < 4; ++it) {
            int i = tid + it * 256;          // 1024 x 16B
            int ci = i >> 3, q = i & 7;
            cpa16(sdst + ci * BST_B + q * 16, wb + (size_t)ci * DD + q * 8);
        }
    };

    issueB(0);
    CP_COMMIT();

    for (int ch = 0; ch < nch; ++ch) {
        if (ch + 1 < nch) { issueB(ch + 1); CP_COMMIT(); }
        if (ch + 1 < nch) asm volatile("cp.async.wait_group 1;" ::: "memory");
        else              asm volatile("cp.async.wait_group 0;" ::: "memory");
        __syncthreads();

        const int m = ch >> 2, dk = ch & 3;
        const int srct = t_ln - m;
        const uint32_t bbase = sb + B_OFF0 + (ch & 1) * B_SZ;

        // per-mt A row base (zero row if t-m < 0)
        uint32_t arow[4];
#pragma unroll
        for (int mt = 0; mt < 4; ++mt) {
            int bl = warpM * 4 + mt;
            arow[mt] = (srct >= 0)
                ? sb + (uint32_t)((bl * 16 + srct) * EST_B + dk * 128 + kh_a * 16)
                : sb + (uint32_t)(ZOFF + dk * 128 + kh_a * 16);
        }

#pragma unroll
        for (int ks = 0; ks < 4; ++ks) {
            uint32_t a[4][4];
#pragma unroll
            for (int mt = 0; mt < 4; ++mt) ldsm4(a[mt], arow[mt] + ks * 32);
            uint32_t bfr[2][4];
#pragma unroll
            for (int n2 = 0; n2 < 2; ++n2) {
                uint32_t ba = bbase + (warpN * 32 + n2 * 16 + n_ln) * BST_B
                            + ks * 32 + kh_b * 16;
                ldsm4(bfr[n2], ba);
            }
#pragma unroll
            for (int mt = 0; mt < 4; ++mt)
#pragma unroll
                for (int ns = 0; ns < 4; ++ns)
                    mma16816(acc[mt][ns], a[mt],
                             bfr[ns >> 1][(ns & 1) * 2],
                             bfr[ns >> 1][(ns & 1) * 2 + 1]);
        }
        __syncthreads();
    }

    // ---- epilogue: acc -> smem (fp32, same 528B stride = 132 floats) ----
    {
        const int r  = lane >> 2;
        const int c2 = (lane & 3) * 2;
#pragma unroll
        for (int mt = 0; mt < 4; ++mt)
#pragma unroll
            for (int ns = 0; ns < 4; ++ns) {
                int row = warpM * 64 + mt * 16 + r;
                int col = warpN * 32 + ns * 8 + c2;
                float2* p0 = (float2*)(smp + row * EST_B + col * 4);
                float2* p1 = (float2*)(smp + (row + 8) * EST_B + col * 4);
                *p0 = make_float2(acc[mt][ns][0], acc[mt][ns][1]);
                *p1 = make_float2(acc[mt][ns][2], acc[mt][ns][3]);
            }
    }
    __syncthreads();

    // ---- gate + 3x fo-pool + t-sum: thread = (bb, c), 4 columns each ----
    const float* acc_s = (const float*)smp;
#pragma unroll
    for (int k = 0; k < 4; ++k) {
        int idx = tid + k * 256;          // 0..1023
        int bb = idx >> 7, cc = idx & 127;
        int b = b0 + bb, c = c0 + cc;
        float bias = conv_b[l * DD + c];
        float h1 = 0.f, h2 = 0.f, h3 = 0.f, o = 0.f;
#pragma unroll
        for (int t = 0; t < TT; ++t) {
            float x = acc_s[(bb * 16 + t) * 132 + cc] + bias;
            float xr = x > 0.f ? x : 0.f;
            float f = sigmoid_pos(xr);
            float e = g_emb[((size_t)b * TT + t) * DD + c];
            h1 = fmaf(f, e - h1, h1);
            h2 = fmaf(f, h1 - h2, h2);
            h3 = fmaf(f, h2 - h3, h3);
            o += h3;
        }
        g_opart[((size_t)l * BB + b) * DD + c] = o;
    }
}

// ---------------- 2) reduce over l -------------------------------------------
__global__ void reduce_o_kernel() {
    int idx = blockIdx.x * blockDim.x + threadIdx.x;   // 0..BB*DD-1
    float o = 0.f;
#pragma unroll
    for (int l = 0; l < LL; ++l) o += g_opart[(size_t)l * BB * DD + idx];
    g_o[idx] = o;
}

// ---------------- 3) z = [o, user_emb] @ fc1_w^T + fc1_b --------------------
__global__ void fc_kernel(const int* __restrict__ user_var,
                          const float* __restrict__ user_emb,
                          const float* __restrict__ fc1_w,
                          const float* __restrict__ fc1_b) {
    __shared__ float cat_s[8][2 * DD];
    int b0 = blockIdx.x * 8;
    int i0 = blockIdx.y * 8;
    int tid = threadIdx.x;
    for (int it = tid; it < 8 * (2 * DD / 4); it += 256) {
        int bb = it >> 7;
        int j4 = it & 127;
        float4 v;
        if (j4 < DD / 4)
            v = ((const float4*)(g_o + (size_t)(b0 + bb) * DD))[j4];
        else
            v = ((const float4*)(user_emb + (size_t)user_var[b0 + bb] * DD))[j4 - DD / 4];
        *(float4*)&cat_s[bb][j4 * 4] = v;
    }
    __syncthreads();
    int warp = tid >> 5, lane = tid & 31;
    int i = i0 + warp;
    float accv[8];
#pragma unroll
    for (int bb = 0; bb < 8; bb++) accv[bb] = 0.f;
    for (int j = lane; j < 2 * DD; j += 32) {
        float w = fc1_w[(size_t)i * (2 * DD) + j];
#pragma unroll
        for (int bb = 0; bb < 8; bb++) accv[bb] += w * cat_s[bb][j];
    }
#pragma unroll
    for (int bb = 0; bb < 8; bb++) {
        float v = accv[bb];
#pragma unroll
        for (int off = 16; off; off >>= 1) v += __shfl_down_sync(0xffffffffu, v, off);
        if (lane == 0) g_z[(size_t)(b0 + bb) * DD + i] = v + fc1_b[i];
    }
}

// ---------------- 4) res[b,n] = W2[item] . z[b] + b2 ------------------------
__global__ void out_kernel(const int* __restrict__ item_var,
                           const float* __restrict__ W2,
                           const float* __restrict__ b2,
                           float* __restrict__ out) {
    int gw = (blockIdx.x * blockDim.x + threadIdx.x) >> 5;
    int lane = threadIdx.x & 31;
    if (gw >= BB * NTGT) return;
    int b = gw >> 5;
    int iv = item_var[gw];
    const float* w = W2 + (size_t)iv * DD;
    const float* zz = g_z + (size_t)b * DD;
    float acc = 0.f;
    for (int d = lane; d < DD; d += 32) acc += w[d] * zz[d];
#pragma unroll
    for (int off = 16; off; off >>= 1) acc += __shfl_down_sync(0xffffffffu, acc, off);
    if (lane == 0) out[gw] = acc + b2[iv];
}

// ---------------- launch ------------------------------------------------------
extern "C" void kernel_launch(void* const* d_in, const int* in_sizes, int n_in,
                              void* d_out, int out_size) {
    const int*   seq_var  = (const int*)d_in[0];
    const int*   user_var = (const int*)d_in[1];
    const int*   item_var = (const int*)d_in[2];
    const float* item_emb = (const float*)d_in[3];
    const float* user_emb = (const float*)d_in[4];
    const float* conv_w   = (const float*)d_in[5];
    const float* conv_b   = (const float*)d_in[6];
    const float* fc1_w    = (const float*)d_in[7];
    const float* fc1_b    = (const float*)d_in[8];
    const float* W2       = (const float*)d_in[9];
    const float* b2       = (const float*)d_in[10];
    float* out = (float*)d_out;

    gather_emb_kernel<<<NROW, 64>>>(seq_var, item_emb);
    wconv_kernel<<<(LL * LL * DD * DD / 4) / 256, 256>>>(conv_w);

    cudaFuncSetAttribute(conv_fused_kernel,
                         cudaFuncAttributeMaxDynamicSharedMemorySize, SMEM_REQ);
    conv_fused_kernel<<<dim3(2, BB / 8, LL), 256, SMEM_REQ>>>(conv_b);

    reduce_o_kernel<<<BB * DD / 256, 256>>>();
    fc_kernel<<<dim3(BB / 8, DD / 8), 256>>>(user_var, user_emb, fc1_w, fc1_b);
    out_kernel<<<(BB * NTGT * 32) / 256, 256>>>(item_var, W2, b2, out);
}